// round 12
// baseline (speedup 1.0000x reference)
#include <cuda_runtime.h>
#include <cuda_bf16.h>

#define N_SAMPLE 12
#define D_FEAT 64
#define NODES_PER_WARP 4
#define PIPE 6   // gathers kept in flight per lane

__device__ __forceinline__ void gather_v8(const float* __restrict__ fp,
                                          unsigned* r) {
    asm volatile("ld.global.nc.L2::evict_last.v8.b32 "
                 "{%0,%1,%2,%3,%4,%5,%6,%7}, [%8];"
                 : "=r"(r[0]),"=r"(r[1]),"=r"(r[2]),"=r"(r[3]),
                   "=r"(r[4]),"=r"(r[5]),"=r"(r[6]),"=r"(r[7])
                 : "l"(fp));
}

template <bool GUARDED>
__global__ void __launch_bounds__(256)
mean_agg_kernel(const float* __restrict__ feature,
                const int* __restrict__ neighbor_idx,
                float* __restrict__ out,
                int n_nodes) {
    int gwarp = (int)((blockIdx.x * (unsigned)blockDim.x + threadIdx.x) >> 5);
    int lane  = threadIdx.x & 31;
    int g     = lane >> 3;   // group 0..3 -> node within warp
    int lg    = lane & 7;    // lane in group: owns 8 floats (32 B) of the row

    int node = gwarp * NODES_PER_WARP + g;
    bool active = true;
    if (GUARDED) {
        active = node < n_nodes;
        if (!active) node = 0;   // clamp so inactive lanes load safely
    }

    // 12 indices per group: lanes 0..7 hold samples 0..7 (idx_a),
    // lanes 0..3 additionally hold samples 8..11 (idx_b).
    const int* ibase = neighbor_idx + (long long)node * N_SAMPLE;
    int idx_a = ibase[lg];
    int idx_b = (lg < 4) ? ibase[8 + lg] : 0;

    const float* fbase = feature + (long long)lg * 8;

    // Copy-free software pipeline: buf[s] written once by its gather and
    // read once at consume; full unroll lets the register allocator rename
    // (peak ~PIPE+1 live buffers of scalar regs — no pair-alignment
    // constraint, unlike the failed b64 variant).
    unsigned buf[N_SAMPLE][8];

    // Prologue: issue samples 0..PIPE-1.
#pragma unroll
    for (int s = 0; s < PIPE; s++) {
        int id = __shfl_sync(0xffffffffu, idx_a, g * 8 + s);
        gather_v8(fbase + (long long)id * D_FEAT, buf[s]);
    }

    float acc[8];
#pragma unroll
    for (int k = 0; k < 8; k++) acc[k] = 0.f;

    // Steady state: issue sample s+PIPE (if any), then consume sample s.
#pragma unroll
    for (int s = 0; s < N_SAMPLE; s++) {
        int s2 = s + PIPE;
        if (s2 < N_SAMPLE) {
            int src = g * 8 + (s2 < 8 ? s2 : s2 - 8);
            int id  = __shfl_sync(0xffffffffu, (s2 < 8) ? idx_a : idx_b, src);
            gather_v8(fbase + (long long)id * D_FEAT, buf[s2]);
        }
#pragma unroll
        for (int k = 0; k < 8; k++) acc[k] += __uint_as_float(buf[s][k]);
    }

    const float inv = 1.0f / (float)N_SAMPLE;
    if (!GUARDED || active) {
        float* op = out + (long long)node * D_FEAT + lg * 8;
        unsigned w[8];
#pragma unroll
        for (int k = 0; k < 8; k++) w[k] = __float_as_uint(acc[k] * inv);
        // Streaming write-once output: don't evict feature lines.
        asm volatile("st.global.L2::evict_first.v8.b32 [%0], "
                     "{%1,%2,%3,%4,%5,%6,%7,%8};"
                     :: "l"(op),
                        "r"(w[0]),"r"(w[1]),"r"(w[2]),"r"(w[3]),
                        "r"(w[4]),"r"(w[5]),"r"(w[6]),"r"(w[7])
                     : "memory");
    }
}

extern "C" void kernel_launch(void* const* d_in, const int* in_sizes, int n_in,
                              void* d_out, int out_size) {
    const float* feature      = (const float*)d_in[0];
    const int*   neighbor_idx = (const int*)d_in[1];
    float*       out          = (float*)d_out;

    int n_nodes = in_sizes[1] / N_SAMPLE;

    const int nodes_per_block = (256 / 32) * NODES_PER_WARP;  // 32
    int blocks = (n_nodes + nodes_per_block - 1) / nodes_per_block;

    if (n_nodes % nodes_per_block == 0) {
        // Exact cover (the benchmark shape: 100000 = 3125 * 32) — no guards.
        mean_agg_kernel<false><<<blocks, 256>>>(feature, neighbor_idx, out, n_nodes);
    } else {
        mean_agg_kernel<true><<<blocks, 256>>>(feature, neighbor_idx, out, n_nodes);
    }
}

// round 13
// speedup vs baseline: 1.1804x; 1.1804x over previous
#include <cuda_runtime.h>
#include <cuda_bf16.h>

#define N_SAMPLE 12
#define D_FEAT 64
#define NODES_PER_WARP 4
#define PIPE 6   // gathers kept in flight per lane

__device__ __forceinline__ void gather_v8(const float* __restrict__ fp,
                                          unsigned* r) {
    asm volatile("ld.global.nc.L2::evict_last.v8.b32 "
                 "{%0,%1,%2,%3,%4,%5,%6,%7}, [%8];"
                 : "=r"(r[0]),"=r"(r[1]),"=r"(r[2]),"=r"(r[3]),
                   "=r"(r[4]),"=r"(r[5]),"=r"(r[6]),"=r"(r[7])
                 : "l"(fp));
}

template <bool GUARDED>
__global__ void __launch_bounds__(256, 4)
mean_agg_kernel(const float* __restrict__ feature,
                const int* __restrict__ neighbor_idx,
                float* __restrict__ out,
                int n_nodes) {
    int gwarp = (int)((blockIdx.x * (unsigned)blockDim.x + threadIdx.x) >> 5);
    int lane  = threadIdx.x & 31;
    int g     = lane >> 3;   // group 0..3 -> node within warp
    int lg    = lane & 7;    // lane in group: owns 8 floats (32 B) of the row

    int node = gwarp * NODES_PER_WARP + g;
    bool active = true;
    if (GUARDED) {
        active = node < n_nodes;
        if (!active) node = 0;   // clamp so inactive lanes load safely
    }

    // 12 indices per group: lanes 0..7 hold samples 0..7 (idx_a),
    // lanes 0..3 additionally hold samples 8..11 (idx_b).
    const int* ibase = neighbor_idx + (long long)node * N_SAMPLE;
    int idx_a = ibase[lg];
    int idx_b = (lg < 4) ? ibase[8 + lg] : 0;

    const float* fbase = feature + (long long)lg * 8;

    // Copy-free software pipeline: buf[s] written once by its gather and
    // read once at consume; full unroll + the 64-reg budget from
    // __launch_bounds__(256,4) lets the allocator rename instead of
    // emitting shift-MOVs, while keeping ~PIPE gathers in flight.
    unsigned buf[N_SAMPLE][8];

    // Prologue: issue samples 0..PIPE-1.
#pragma unroll
    for (int s = 0; s < PIPE; s++) {
        int id = __shfl_sync(0xffffffffu, idx_a, g * 8 + s);
        gather_v8(fbase + (long long)id * D_FEAT, buf[s]);
    }

    float acc[8];
#pragma unroll
    for (int k = 0; k < 8; k++) acc[k] = 0.f;

    // Steady state: issue sample s+PIPE (if any), then consume sample s.
#pragma unroll
    for (int s = 0; s < N_SAMPLE; s++) {
        int s2 = s + PIPE;
        if (s2 < N_SAMPLE) {
            int src = g * 8 + (s2 < 8 ? s2 : s2 - 8);
            int id  = __shfl_sync(0xffffffffu, (s2 < 8) ? idx_a : idx_b, src);
            gather_v8(fbase + (long long)id * D_FEAT, buf[s2]);
        }
#pragma unroll
        for (int k = 0; k < 8; k++) acc[k] += __uint_as_float(buf[s][k]);
    }

    const float inv = 1.0f / (float)N_SAMPLE;
    if (!GUARDED || active) {
        float* op = out + (long long)node * D_FEAT + lg * 8;
        unsigned w[8];
#pragma unroll
        for (int k = 0; k < 8; k++) w[k] = __float_as_uint(acc[k] * inv);
        // Streaming write-once output: don't evict feature lines.
        asm volatile("st.global.L2::evict_first.v8.b32 [%0], "
                     "{%1,%2,%3,%4,%5,%6,%7,%8};"
                     :: "l"(op),
                        "r"(w[0]),"r"(w[1]),"r"(w[2]),"r"(w[3]),
                        "r"(w[4]),"r"(w[5]),"r"(w[6]),"r"(w[7])
                     : "memory");
    }
}

extern "C" void kernel_launch(void* const* d_in, const int* in_sizes, int n_in,
                              void* d_out, int out_size) {
    const float* feature      = (const float*)d_in[0];
    const int*   neighbor_idx = (const int*)d_in[1];
    float*       out          = (float*)d_out;

    int n_nodes = in_sizes[1] / N_SAMPLE;

    const int nodes_per_block = (256 / 32) * NODES_PER_WARP;  // 32
    int blocks = (n_nodes + nodes_per_block - 1) / nodes_per_block;

    if (n_nodes % nodes_per_block == 0) {
        // Exact cover (the benchmark shape: 100000 = 3125 * 32) — no guards.
        mean_agg_kernel<false><<<blocks, 256>>>(feature, neighbor_idx, out, n_nodes);
    } else {
        mean_agg_kernel<true><<<blocks, 256>>>(feature, neighbor_idx, out, n_nodes);
    }
}